// round 17
// baseline (speedup 1.0000x reference)
#include <cuda_runtime.h>

#define B_ 4
#define F_ 1025
#define C_ 6
#define T_ 1000
#define P_ 500          // T_/2 float2 positions
#define THREADS 128
#define GRID 1025       // 4 problems per CTA, single wave (148*7=1036 slots)
#define PER_CTA 4

#define DIAG_EPS 1e-7f
#define EPS_ 1e-8f
#define PSD_EPS 1e-15f
#define ACC_N 74
// s_acc: [0..20] s_re, [21..35] s_im, [36..56] n_re, [57..71] n_im, [72] sum_ms, [73] sum_mn

__device__ __forceinline__ float2 cdiv(float2 a, float2 b) {
    float inv = 1.0f / (b.x*b.x + b.y*b.y);
    return make_float2((a.x*b.x + a.y*b.y)*inv, (a.y*b.x - a.x*b.y)*inv);
}

// ---- packed fp32x2 ops (sm_103a) ----
__device__ __forceinline__ float2 fmul2(float2 a, float2 b) {
    float2 d;
    asm("{\n\t.reg .b64 ra,rb,rd;\n\t"
        "mov.b64 ra,{%2,%3};\n\tmov.b64 rb,{%4,%5};\n\t"
        "mul.rn.f32x2 rd, ra, rb;\n\t"
        "mov.b64 {%0,%1}, rd;\n\t}"
        : "=f"(d.x), "=f"(d.y) : "f"(a.x), "f"(a.y), "f"(b.x), "f"(b.y));
    return d;
}
__device__ __forceinline__ float2 ffma2(float2 a, float2 b, float2 c) {
    float2 d;
    asm("{\n\t.reg .b64 ra,rb,rc,rd;\n\t"
        "mov.b64 ra,{%2,%3};\n\tmov.b64 rb,{%4,%5};\n\tmov.b64 rc,{%6,%7};\n\t"
        "fma.rn.f32x2 rd, ra, rb, rc;\n\t"
        "mov.b64 {%0,%1}, rd;\n\t}"
        : "=f"(d.x), "=f"(d.y)
        : "f"(a.x), "f"(a.y), "f"(b.x), "f"(b.y), "f"(c.x), "f"(c.y));
    return d;
}
__device__ __forceinline__ float2 fsub2(float2 a, float2 b) {
    float2 d;
    asm("{\n\t.reg .b64 ra,rb,rd;\n\t"
        "mov.b64 ra,{%2,%3};\n\tmov.b64 rb,{%4,%5};\n\t"
        "sub.rn.f32x2 rd, ra, rb;\n\t"
        "mov.b64 {%0,%1}, rd;\n\t}"
        : "=f"(d.x), "=f"(d.y) : "f"(a.x), "f"(a.y), "f"(b.x), "f"(b.y));
    return d;
}

// Per-warp pair configuration via constexpr functions (device-safe).
template<int WID> struct WCfg;
template<> struct WCfg<0> {                      // pairs within {0,1,2}
    static constexpr int NCH = 3, NP = 6;
    static constexpr bool SUMM = false;
    static constexpr __host__ __device__ int ch(int i){ const int v[3]={0,1,2}; return v[i]; }
    static constexpr __host__ __device__ int pa(int k){ const int v[6]={0,0,0,1,1,2}; return v[k]; }
    static constexpr __host__ __device__ int pb(int k){ const int v[6]={0,1,2,1,2,2}; return v[k]; }
    static constexpr __host__ __device__ int gc(int k){ const int v[6]={0,0,0,1,1,2}; return v[k]; }
    static constexpr __host__ __device__ int ge(int k){ const int v[6]={0,1,2,1,2,2}; return v[k]; }
};
template<> struct WCfg<1> {                      // pairs within {3,4,5}
    static constexpr int NCH = 3, NP = 6;
    static constexpr bool SUMM = false;
    static constexpr __host__ __device__ int ch(int i){ const int v[3]={3,4,5}; return v[i]; }
    static constexpr __host__ __device__ int pa(int k){ const int v[6]={0,0,0,1,1,2}; return v[k]; }
    static constexpr __host__ __device__ int pb(int k){ const int v[6]={0,1,2,1,2,2}; return v[k]; }
    static constexpr __host__ __device__ int gc(int k){ const int v[6]={3,3,3,4,4,5}; return v[k]; }
    static constexpr __host__ __device__ int ge(int k){ const int v[6]={3,4,5,4,5,5}; return v[k]; }
};
template<> struct WCfg<2> {                      // cross pairs, part 1
    static constexpr int NCH = 5, NP = 5;
    static constexpr bool SUMM = false;
    static constexpr __host__ __device__ int ch(int i){ const int v[5]={0,1,3,4,5}; return v[i]; }
    static constexpr __host__ __device__ int pa(int k){ const int v[5]={0,0,0,1,1}; return v[k]; }
    static constexpr __host__ __device__ int pb(int k){ const int v[5]={2,3,4,2,3}; return v[k]; }
    static constexpr __host__ __device__ int gc(int k){ const int v[5]={0,0,0,1,1}; return v[k]; }
    static constexpr __host__ __device__ int ge(int k){ const int v[5]={3,4,5,3,4}; return v[k]; }
};
template<> struct WCfg<3> {                      // cross pairs, part 2 + mask sums
    static constexpr int NCH = 5, NP = 4;
    static constexpr bool SUMM = true;
    static constexpr __host__ __device__ int ch(int i){ const int v[5]={1,2,3,4,5}; return v[i]; }
    static constexpr __host__ __device__ int pa(int k){ const int v[4]={0,1,1,1}; return v[k]; }
    static constexpr __host__ __device__ int pb(int k){ const int v[4]={4,2,3,4}; return v[k]; }
    static constexpr __host__ __device__ int gc(int k){ const int v[4]={1,2,2,2}; return v[k]; }
    static constexpr __host__ __device__ int ge(int k){ const int v[4]={5,3,4,5}; return v[k]; }
};

template<int WID>
__device__ __forceinline__ void psd_w(
    const float2* __restrict__ sr2, const float2* __restrict__ si2,
    const float2* __restrict__ ms2, const float2* __restrict__ mn2,
    int lane, float* __restrict__ s_acc)
{
    using W = WCfg<WID>;
    // Packed accumulators: lane-x holds even-t partial, lane-y odd-t partial.
    float2 asr[W::NP], anr[W::NP], asi[W::NP], ani[W::NP];
    #pragma unroll
    for (int k = 0; k < W::NP; ++k) {
        asr[k]=make_float2(0.f,0.f); anr[k]=make_float2(0.f,0.f);
        asi[k]=make_float2(0.f,0.f); ani[k]=make_float2(0.f,0.f);
    }
    float2 sms = make_float2(0.f,0.f), smn = make_float2(0.f,0.f);

    for (int p = lane; p < P_; p += 32) {
        float2 xr[W::NCH], xi[W::NCH];
        #pragma unroll
        for (int i = 0; i < W::NCH; ++i) {
            xr[i] = sr2[W::ch(i)*P_ + p];
            xi[i] = si2[W::ch(i)*P_ + p];
        }
        const float2 m_s = ms2[p];
        const float2 m_n = mn2[p];
        if (W::SUMM) {
            sms.x += m_s.x; sms.y += m_s.y;
            smn.x += m_n.x; smn.y += m_n.y;
        }

        #pragma unroll
        for (int k = 0; k < W::NP; ++k) {
            const int a = W::pa(k), b = W::pb(k);
            // re: xr_a*xr_b + xi_a*xi_b (packed over 2 timesteps)
            float2 r01 = ffma2(xi[a], xi[b], fmul2(xr[a], xr[b]));
            asr[k] = ffma2(m_s, r01, asr[k]);
            anr[k] = ffma2(m_n, r01, anr[k]);
            if (W::gc(k) != W::ge(k)) {
                // im: xi_a*xr_b - xr_a*xi_b (packed)
                float2 i01 = fsub2(fmul2(xi[a], xr[b]), fmul2(xr[a], xi[b]));
                asi[k] = ffma2(m_s, i01, asi[k]);
                ani[k] = ffma2(m_n, i01, ani[k]);
            }
        }
    }

    // Collapse packed -> scalar, then standard warp shuffle tree.
    float csr[W::NP], cnr[W::NP], csi[W::NP], cni[W::NP];
    #pragma unroll
    for (int k = 0; k < W::NP; ++k) {
        csr[k] = asr[k].x + asr[k].y;
        cnr[k] = anr[k].x + anr[k].y;
        csi[k] = asi[k].x + asi[k].y;
        cni[k] = ani[k].x + ani[k].y;
    }
    float ssum = sms.x + sms.y, nsum = smn.x + smn.y;

    #pragma unroll
    for (int off = 16; off > 0; off >>= 1) {
        #pragma unroll
        for (int k = 0; k < W::NP; ++k) {
            csr[k] += __shfl_down_sync(0xffffffffu, csr[k], off);
            cnr[k] += __shfl_down_sync(0xffffffffu, cnr[k], off);
            if (W::gc(k) != W::ge(k)) {
                csi[k] += __shfl_down_sync(0xffffffffu, csi[k], off);
                cni[k] += __shfl_down_sync(0xffffffffu, cni[k], off);
            }
        }
        if (W::SUMM) {
            ssum += __shfl_down_sync(0xffffffffu, ssum, off);
            nsum += __shfl_down_sync(0xffffffffu, nsum, off);
        }
    }
    if (lane == 0) {
        #pragma unroll
        for (int k = 0; k < W::NP; ++k) {
            const int c = W::gc(k), e = W::ge(k);
            const int kg = c*(11 - c)/2 + e;
            s_acc[kg]      = csr[k];
            s_acc[36 + kg] = cnr[k];
            if (c != e) {
                const int kig = kg - (c + 1);
                s_acc[21 + kig] = csi[k];
                s_acc[57 + kig] = cni[k];
            }
        }
        if (W::SUMM) { s_acc[72] = ssum; s_acc[73] = nsum; }
    }
}

__global__ __launch_bounds__(THREADS, 7)
void mvdr_kernel(const float* __restrict__ spec_r,
                 const float* __restrict__ spec_i,
                 const float* __restrict__ mask_s,
                 const float* __restrict__ mask_n,
                 float* __restrict__ out, int out_mode)
{
    __shared__ float  s_acc[ACC_N];
    __shared__ float2 M[C_][2*C_];
    __shared__ float2 fac[C_];
    __shared__ float2 wc[C_];

    const int tid  = threadIdx.x;
    const int lane = tid & 31;
    const int wid  = tid >> 5;

    for (int t = 0; t < PER_CTA; ++t) {
        const int bf = blockIdx.x * PER_CTA + t;

        const float2* sr2 = (const float2*)(spec_r + (size_t)bf * (C_*T_));
        const float2* si2 = (const float2*)(spec_i + (size_t)bf * (C_*T_));
        const float2* ms2 = (const float2*)(mask_s + (size_t)bf * T_);
        const float2* mn2 = (const float2*)(mask_n + (size_t)bf * T_);

        // ---- Phase 1+2: packed-f32x2 PSD accumulation, warp-local reduce ----
        if      (wid == 0) psd_w<0>(sr2, si2, ms2, mn2, lane, s_acc);
        else if (wid == 1) psd_w<1>(sr2, si2, ms2, mn2, lane, s_acc);
        else if (wid == 2) psd_w<2>(sr2, si2, ms2, mn2, lane, s_acc);
        else               psd_w<3>(sr2, si2, ms2, mn2, lane, s_acc);
        __syncthreads();

        // ---- Phase 3: build [psd_n | psd_s], 72-thread Gaussian elimination ----
        if (tid < 72) {
            const int r  = tid / 12;
            const int j  = tid % 12;
            const bool isS = (j >= 6);
            const int c2 = isS ? (j - 6) : j;
            const int cc = (r < c2) ? r : c2;
            const int ee = (r < c2) ? c2 : r;
            const int k  = cc*(11 - cc)/2 + ee;
            const int ki = k - (cc + 1);

            const float norm = isS ? (1.0f/(s_acc[72] + PSD_EPS))
                                   : (1.0f/(s_acc[73] + PSD_EPS));
            const int reBase = isS ? 0 : 36;
            const int imBase = isS ? 21 : 57;

            float re = s_acc[reBase + k] * norm;
            float im = (r == c2) ? 0.0f : s_acc[imBase + ki] * norm;
            if (r > c2) im = -im;

            if (!isS && r == c2) {
                float trn = (s_acc[36+0] + s_acc[36+6] + s_acc[36+11] +
                             s_acc[36+15] + s_acc[36+18] + s_acc[36+20]) *
                            (1.0f/(s_acc[73] + PSD_EPS));
                re += trn * DIAG_EPS + EPS_;
            }
            M[r][j] = make_float2(re, im);
        }
        __syncthreads();

        const int r = tid / 12;
        const int j = tid % 12;
        #pragma unroll
        for (int kk = 0; kk < C_ - 1; ++kk) {
            if (tid < 72 && j == kk && r > kk)
                fac[r] = cdiv(M[r][kk], M[kk][kk]);
            __syncthreads();
            if (tid < 72 && r > kk) {
                float2 f = fac[r];
                float2 p = M[kk][j];
                float2 v = M[r][j];
                v.x -= f.x*p.x - f.y*p.y;
                v.y -= f.x*p.y + f.y*p.x;
                M[r][j] = v;
            }
            __syncthreads();
        }

        if (tid < C_) {
            #pragma unroll
            for (int kk = C_ - 1; kk >= 0; --kk) {
                float2 acc = M[kk][6 + tid];
                #pragma unroll
                for (int i = C_ - 1; i >= 1; --i) {
                    if (i > kk) {
                        float2 a = M[kk][i];
                        float2 w = M[i][6 + tid];
                        acc.x -= a.x*w.x - a.y*w.y;
                        acc.y -= a.x*w.y + a.y*w.x;
                    }
                }
                M[kk][6 + tid] = cdiv(acc, M[kk][kk]);
            }
        }
        __syncthreads();

        if (tid == 0) {
            float2 tr = make_float2(0.f, 0.f);
            #pragma unroll
            for (int d = 0; d < C_; ++d) { tr.x += M[d][6+d].x; tr.y += M[d][6+d].y; }
            float2 denom = make_float2(tr.x + EPS_, tr.y);
            #pragma unroll
            for (int c = 0; c < C_; ++c) {
                float2 w = cdiv(M[c][6 + 0], denom);   // REF_CHANNEL = 0
                wc[c] = make_float2(w.x, -w.y);        // conj(w)
            }
        }
        __syncthreads();

        // ---- Phase 4: beamform, float2 re-read (L1/L2-resident) ----
        float2 wreg[C_];
        #pragma unroll
        for (int c = 0; c < C_; ++c) wreg[c] = wc[c];

        if (out_mode == 0) {
            float4* o4 = (float4*)out + (size_t)bf * P_;
            for (int p = tid; p < P_; p += THREADS) {
                float ar0 = 0.f, ai0 = 0.f, ar1 = 0.f, ai1 = 0.f;
                #pragma unroll
                for (int c = 0; c < C_; ++c) {
                    float2 xr = sr2[c*P_ + p];
                    float2 xi = si2[c*P_ + p];
                    ar0 += wreg[c].x*xr.x - wreg[c].y*xi.x;
                    ai0 += wreg[c].x*xi.x + wreg[c].y*xr.x;
                    ar1 += wreg[c].x*xr.y - wreg[c].y*xi.y;
                    ai1 += wreg[c].x*xi.y + wreg[c].y*xr.y;
                }
                o4[p] = make_float4(ar0, ai0, ar1, ai1);
            }
        } else {
            float2* o2 = (float2*)(out + (size_t)bf * T_);
            for (int p = tid; p < P_; p += THREADS) {
                float ar0 = 0.f, ar1 = 0.f;
                #pragma unroll
                for (int c = 0; c < C_; ++c) {
                    float2 xr = sr2[c*P_ + p];
                    float2 xi = si2[c*P_ + p];
                    ar0 += wreg[c].x*xr.x - wreg[c].y*xi.x;
                    ar1 += wreg[c].x*xr.y - wreg[c].y*xi.y;
                }
                o2[p] = make_float2(ar0, ar1);
            }
        }
        __syncthreads();   // smem hygiene before next problem
    }
}

extern "C" void kernel_launch(void* const* d_in, const int* in_sizes, int n_in,
                              void* d_out, int out_size) {
    const long long SPEC_N = (long long)B_ * F_ * C_ * T_;   // 24,600,000
    const long long MASK_N = (long long)B_ * F_ * T_;        //  4,100,000

    const float* ptr[4] = {nullptr, nullptr, nullptr, nullptr};
    for (int i = 0; i < n_in; ++i) {
        long long sz = (long long)in_sizes[i];
        const float* p = (const float*)d_in[i];
        if (sz == SPEC_N) {
            if (!ptr[0]) ptr[0] = p; else if (!ptr[1]) ptr[1] = p;
        } else if (sz == MASK_N) {
            if (!ptr[2]) ptr[2] = p; else if (!ptr[3]) ptr[3] = p;
        }
    }
    for (int s = 0; s < 4; ++s) {
        if (!ptr[s]) {
            int i = (s < n_in) ? s : (n_in - 1);
            ptr[s] = (const float*)d_in[i];
        }
    }

    const int out_mode = ((long long)out_size >= 2 * MASK_N) ? 0 : 1;

    mvdr_kernel<<<GRID, THREADS>>>(ptr[0], ptr[1], ptr[2], ptr[3],
                                   (float*)d_out, out_mode);
}